// round 1
// baseline (speedup 1.0000x reference)
#include <cuda_runtime.h>
#include <cuda_bf16.h>

// Problem constants (from reference): B=16384, IN_DIM=1024, D=256, C=100
#define Bsz   16384
#define KDIM  1024
#define DDIM  256
#define CNUM  100
#define CPAD  112   // pad classes to 16*7 so the inner loop has no guards

// Scratch for Z = x@W + b  (16 MB, static device global: allocation-free)
__device__ float g_Z[Bsz * DDIM];

// ---------------------------------------------------------------------------
// Kernel 1: Z = x @ W + b    (M=16384, N=256, K=1024) fp32 SGEMM
// BM=128, BN=128, BK=8, 256 threads, 8x8 register tile per thread.
// grid = (N/128=2, M/128=128); x-fastest so the two N-blocks of the same
// M-rows are co-resident and share the x tile in L2.
// ---------------------------------------------------------------------------
__global__ void __launch_bounds__(256, 2)
gemm_bias_kernel(const float* __restrict__ A,   // [Bsz, KDIM]
                 const float* __restrict__ Wm,  // [KDIM, DDIM]
                 const float* __restrict__ bias)// [DDIM]
{
    __shared__ float As[8][128];   // transposed A tile: As[k][m]
    __shared__ float Bs[8][128];   // Bs[k][n]

    const int tid = threadIdx.x;
    const int tx  = tid & 15;      // N direction (16 thread-cols * 8 = 128)
    const int ty  = tid >> 4;      // M direction (16 thread-rows * 8 = 128)

    const int mBase = blockIdx.y * 128;
    const int nBase = blockIdx.x * 128;

    // Global-load mapping: one float4 per thread per tile for each operand.
    const int arow = tid >> 1;          // 0..127 (row within A tile)
    const int acol = (tid & 1) * 4;     // 0 or 4 (k within BK=8)
    const int brow = tid >> 5;          // 0..7   (k within BK=8)
    const int bcol = (tid & 31) * 4;    // 0..124 (n within tile)

    float acc[8][8];
#pragma unroll
    for (int i = 0; i < 8; i++)
#pragma unroll
        for (int j = 0; j < 8; j++) acc[i][j] = 0.0f;

    // Prefetch first tiles
    float4 av = *reinterpret_cast<const float4*>(
        &A[(size_t)(mBase + arow) * KDIM + acol]);
    float4 bv = *reinterpret_cast<const float4*>(
        &Wm[(size_t)brow * DDIM + nBase + bcol]);

    for (int kt = 0; kt < KDIM; kt += 8) {
        // store staged tiles
        As[acol + 0][arow] = av.x;
        As[acol + 1][arow] = av.y;
        As[acol + 2][arow] = av.z;
        As[acol + 3][arow] = av.w;
        *reinterpret_cast<float4*>(&Bs[brow][bcol]) = bv;
        __syncthreads();

        // prefetch next tiles while computing
        if (kt + 8 < KDIM) {
            av = *reinterpret_cast<const float4*>(
                &A[(size_t)(mBase + arow) * KDIM + (kt + 8) + acol]);
            bv = *reinterpret_cast<const float4*>(
                &Wm[(size_t)(kt + 8 + brow) * DDIM + nBase + bcol]);
        }

#pragma unroll
        for (int kk = 0; kk < 8; kk++) {
            float a[8], bb[8];
#pragma unroll
            for (int i = 0; i < 8; i++) a[i]  = As[kk][ty * 8 + i];
#pragma unroll
            for (int j = 0; j < 8; j++) bb[j] = Bs[kk][tx * 8 + j];
#pragma unroll
            for (int i = 0; i < 8; i++)
#pragma unroll
                for (int j = 0; j < 8; j++)
                    acc[i][j] += a[i] * bb[j];
        }
        __syncthreads();
    }

    // Epilogue: add bias, store Z (two float4 per row)
    float bj[8];
#pragma unroll
    for (int j = 0; j < 8; j++) bj[j] = bias[nBase + tx * 8 + j];

#pragma unroll
    for (int i = 0; i < 8; i++) {
        const int row = mBase + ty * 8 + i;
        float* zp = &g_Z[(size_t)row * DDIM + nBase + tx * 8];
        float4 v0 = make_float4(acc[i][0] + bj[0], acc[i][1] + bj[1],
                                acc[i][2] + bj[2], acc[i][3] + bj[3]);
        float4 v1 = make_float4(acc[i][4] + bj[4], acc[i][5] + bj[5],
                                acc[i][6] + bj[6], acc[i][7] + bj[7]);
        reinterpret_cast<float4*>(zp)[0] = v0;
        reinterpret_cast<float4*>(zp)[1] = v1;
    }
}

// ---------------------------------------------------------------------------
// Kernel 2: out[r][c] = -( |Z_r|^2 - 2 Z_r.P_c + |P_c|^2 ) / D
// Block = 64 Z-rows x all 100 classes. Z tile + full (padded) P in smem.
// 256 threads as 16x16; each thread: 4 rows x 7 class-columns register tile.
// ---------------------------------------------------------------------------
#define LDS_PITCH 257   // odd pitch -> conflict-free column reads
#define SMEM_FLOATS (64 * LDS_PITCH + CPAD * LDS_PITCH + 64 + CPAD)
#define SMEM_BYTES  (SMEM_FLOATS * 4)

__global__ void __launch_bounds__(256)
dist_kernel(const float* __restrict__ P,   // [CNUM, DDIM]
            float* __restrict__ out)       // [Bsz, CNUM]
{
    extern __shared__ float sm[];
    float* Zs    = sm;                        // [64][LDS_PITCH]
    float* Ps    = sm + 64 * LDS_PITCH;       // [CPAD][LDS_PITCH]
    float* rowsq = Ps + CPAD * LDS_PITCH;     // [64]
    float* pn    = rowsq + 64;                // [CPAD]

    const int tid   = threadIdx.x;
    const int mBase = blockIdx.x * 64;

    // Load Z tile (coalesced)
    for (int idx = tid; idx < 64 * DDIM; idx += 256) {
        int r = idx >> 8, k = idx & 255;
        Zs[r * LDS_PITCH + k] = g_Z[(size_t)(mBase + r) * DDIM + k];
    }
    // Load P, zero-pad rows [100,112)
    for (int idx = tid; idx < CPAD * DDIM; idx += 256) {
        int r = idx >> 8, k = idx & 255;
        Ps[r * LDS_PITCH + k] = (r < CNUM) ? P[(size_t)r * DDIM + k] : 0.0f;
    }
    __syncthreads();

    // Row norms of Z (threads 0..63) and P (threads 64..175)
    if (tid < 64) {
        float s = 0.0f;
#pragma unroll 8
        for (int k = 0; k < DDIM; k++) {
            float v = Zs[tid * LDS_PITCH + k];
            s += v * v;
        }
        rowsq[tid] = s;
    } else if (tid < 64 + CPAD) {
        int c = tid - 64;
        float s = 0.0f;
#pragma unroll 8
        for (int k = 0; k < DDIM; k++) {
            float v = Ps[c * LDS_PITCH + k];
            s += v * v;
        }
        pn[c] = s;
    }
    __syncthreads();

    const int tx = tid & 15;   // class direction: c = tx + 16*j, j in [0,7)
    const int ty = tid >> 4;   // row direction:   r = ty*4 + i

    float acc[4][7];
#pragma unroll
    for (int i = 0; i < 4; i++)
#pragma unroll
        for (int j = 0; j < 7; j++) acc[i][j] = 0.0f;

    const float* z0 = &Zs[(ty * 4 + 0) * LDS_PITCH];
    const float* z1 = &Zs[(ty * 4 + 1) * LDS_PITCH];
    const float* z2 = &Zs[(ty * 4 + 2) * LDS_PITCH];
    const float* z3 = &Zs[(ty * 4 + 3) * LDS_PITCH];

#pragma unroll 4
    for (int k = 0; k < DDIM; k++) {
        float a0 = z0[k], a1 = z1[k], a2 = z2[k], a3 = z3[k];
#pragma unroll
        for (int j = 0; j < 7; j++) {
            float p = Ps[(tx + 16 * j) * LDS_PITCH + k];
            acc[0][j] += a0 * p;
            acc[1][j] += a1 * p;
            acc[2][j] += a2 * p;
            acc[3][j] += a3 * p;
        }
    }

    const float invd = 1.0f / (float)DDIM;
#pragma unroll
    for (int i = 0; i < 4; i++) {
        const int r  = ty * 4 + i;
        const float rs = rowsq[r];
        const size_t rowOff = (size_t)(mBase + r) * CNUM;
#pragma unroll
        for (int j = 0; j < 7; j++) {
            int c = tx + 16 * j;
            if (c < CNUM)
                out[rowOff + c] = -(rs - 2.0f * acc[i][j] + pn[c]) * invd;
        }
    }
}

// ---------------------------------------------------------------------------
// Launch. Inputs (metadata order): x [B,IN_DIM], W [IN_DIM,D], b [D], P [C,D]
// Output: float [B, C]
// ---------------------------------------------------------------------------
extern "C" void kernel_launch(void* const* d_in, const int* in_sizes, int n_in,
                              void* d_out, int out_size)
{
    const float* x  = (const float*)d_in[0];
    const float* W  = (const float*)d_in[1];
    const float* b  = (const float*)d_in[2];
    const float* P  = (const float*)d_in[3];
    float* out = (float*)d_out;

    // 181,632 B dynamic smem for dist_kernel (> 48 KB default); attribute set
    // is idempotent and not a stream op -> capture-safe.
    cudaFuncSetAttribute(dist_kernel,
                         cudaFuncAttributeMaxDynamicSharedMemorySize,
                         SMEM_BYTES);

    dim3 g1(DDIM / 128, Bsz / 128);   // (2, 128)
    gemm_bias_kernel<<<g1, 256>>>(x, W, b);

    dist_kernel<<<Bsz / 64, 256, SMEM_BYTES>>>(P, out);
}

// round 3
// speedup vs baseline: 3.5853x; 3.5853x over previous
#include <cuda_runtime.h>
#include <cstdint>

// Problem: B=16384, IN_DIM=1024, D=256, C=100
#define Bsz    16384
#define KDIM   1024
#define DDIM   256
#define CNUM   100
#define CPAD   112

#define BM 128
#define BN 256          // full D per CTA
#define BK 32
#define NITER (KDIM / BK)   // 32

// smem strides (floats), chosen bank-conflict-free for the mma frag patterns
#define ASTRIDE 36      // A tile rows: bank = (4*(lane/4)+lane%4+C)%32, distinct
#define BSTRIDE 264     // B tile rows: bank = (8k+n)%32, distinct
#define ZSTRIDE 260     // Z smem (MMA2 A operand)
#define PSTRIDE 36      // P chunk (MMA2 B operand)

#define A_BYTES (BM * ASTRIDE * 4)        // 18432
#define B_BYTES (BK * BSTRIDE * 4)        // 33792
#define STAGE_BYTES (A_BYTES + B_BYTES)   // 52224
#define STAGE_F (STAGE_BYTES / 4)

#define ZS_F   (BM * ZSTRIDE)             // 33280 floats
#define PCH_F  (CPAD * PSTRIDE)           // 4032 floats (one 32-k chunk)
#define DYN_BYTES ((ZS_F + 2 * PCH_F) * 4)   // 165376 (> 3*STAGE_BYTES=156672)

// ---------------------------------------------------------------------------
__device__ __forceinline__ uint32_t smem_u32(const void* p) {
    uint32_t a;
    asm("{ .reg .u64 t; cvta.to.shared.u64 t, %1; cvt.u32.u64 %0, t; }"
        : "=r"(a) : "l"(p));
    return a;
}

#define CP_ASYNC16(dst, src) \
    asm volatile("cp.async.cg.shared.global [%0], [%1], 16;" \
                 :: "r"(dst), "l"(src) : "memory")
#define CP_COMMIT() asm volatile("cp.async.commit_group;" ::: "memory")
#define CP_WAIT1()  asm volatile("cp.async.wait_group 1;" ::: "memory")
#define CP_WAIT0()  asm volatile("cp.async.wait_group 0;" ::: "memory")

__device__ __forceinline__ uint32_t f2tf(float x) {
    uint32_t r;
    asm("cvt.rna.tf32.f32 %0, %1;" : "=r"(r) : "f"(x));
    return r;
}

#define MMA_TF32(d, a, b) \
    asm volatile("mma.sync.aligned.m16n8k8.row.col.f32.tf32.tf32.f32 " \
        "{%0,%1,%2,%3}, {%4,%5,%6,%7}, {%8,%9}, {%0,%1,%2,%3};" \
        : "+f"((d)[0]), "+f"((d)[1]), "+f"((d)[2]), "+f"((d)[3]) \
        : "r"((a)[0]), "r"((a)[1]), "r"((a)[2]), "r"((a)[3]), \
          "r"((b)[0]), "r"((b)[1]))

// ---------------------------------------------------------------------------
// Fused kernel: per CTA, 128 rows.
//  Phase 1: Z[128,256] = x@W (tf32 mma.sync, 3-stage cp.async pipeline)
//  Epilogue A: +bias, rowsq via shfl+smem atomics, Z -> smem
//  Phase 2: dot[128,112] = Z @ P^T (tf32 mma.sync, P chunks double-buffered)
//  Epilogue B: out = (2*dot - rowsq - |P|^2) / 256
// ---------------------------------------------------------------------------
__global__ void __launch_bounds__(256, 1)
fused_kernel(const float* __restrict__ x,
             const float* __restrict__ W,
             const float* __restrict__ bias,
             const float* __restrict__ P,
             float* __restrict__ out)
{
    extern __shared__ float dyn[];
    __shared__ float s_bias[DDIM];
    __shared__ float srow[BM];
    __shared__ float s_pn[CPAD];

    const int tid  = threadIdx.x;
    const int wid  = tid >> 5;
    const int lane = tid & 31;
    const int mBase = blockIdx.x * BM;

    const int warp_m = wid >> 2;   // 0..1 (64 rows each)
    const int warp_n = wid & 3;    // 0..3 (64 cols each)

    s_bias[tid] = bias[tid];       // 256 threads == DDIM
    if (tid < BM) srow[tid] = 0.0f;

    const uint32_t dynb = smem_u32(dyn);

    // ---- stage loader (GEMM1) ----
    auto load_stage = [&](int kIter, int slot) {
        const int k0 = kIter * BK;
        const uint32_t aB = dynb + slot * STAGE_BYTES;
        const uint32_t bB = aB + A_BYTES;
#pragma unroll
        for (int i = 0; i < 4; i++) {           // A: 128 rows x 32 floats
            const int c = tid + (i << 8);
            const int row = c >> 3, seg = c & 7;
            CP_ASYNC16(aB + row * (ASTRIDE * 4) + seg * 16,
                       x + (size_t)(mBase + row) * KDIM + k0 + seg * 4);
        }
#pragma unroll
        for (int i = 0; i < 8; i++) {           // B: 32 k-rows x 256 floats
            const int c = tid + (i << 8);
            const int k = c >> 6, seg = c & 63;
            CP_ASYNC16(bB + k * (BSTRIDE * 4) + seg * 16,
                       W + (size_t)(k0 + k) * DDIM + seg * 4);
        }
    };

    load_stage(0, 0); CP_COMMIT();
    load_stage(1, 1); CP_COMMIT();

    float acc[4][8][4];
#pragma unroll
    for (int i = 0; i < 4; i++)
#pragma unroll
        for (int j = 0; j < 8; j++)
#pragma unroll
            for (int r = 0; r < 4; r++) acc[i][j][r] = 0.0f;

    const int lq = lane >> 2;      // lane/4
    const int lr = lane & 3;       // lane%4

    // ---- GEMM1 mainloop ----
    for (int it = 0; it < NITER; ++it) {
        if (it == NITER - 1) { CP_WAIT0(); } else { CP_WAIT1(); }
        __syncthreads();

        const float* As = dyn + (it % 3) * STAGE_F;
        const float* Bs = As + A_BYTES / 4;

#pragma unroll
        for (int kk = 0; kk < 4; kk++) {
            uint32_t au[4][4], bu[8][2];
#pragma unroll
            for (int mi = 0; mi < 4; mi++) {
                const int row = warp_m * 64 + mi * 16 + lq;
                const int kc  = kk * 8 + lr;
                au[mi][0] = f2tf(As[row * ASTRIDE + kc]);
                au[mi][1] = f2tf(As[(row + 8) * ASTRIDE + kc]);
                au[mi][2] = f2tf(As[row * ASTRIDE + kc + 4]);
                au[mi][3] = f2tf(As[(row + 8) * ASTRIDE + kc + 4]);
            }
#pragma unroll
            for (int nj = 0; nj < 8; nj++) {
                const int col = warp_n * 64 + nj * 8 + lq;
                const int kc  = kk * 8 + lr;
                bu[nj][0] = f2tf(Bs[kc * BSTRIDE + col]);
                bu[nj][1] = f2tf(Bs[(kc + 4) * BSTRIDE + col]);
            }
#pragma unroll
            for (int mi = 0; mi < 4; mi++)
#pragma unroll
                for (int nj = 0; nj < 8; nj++)
                    MMA_TF32(acc[mi][nj], au[mi], bu[nj]);
        }
        __syncthreads();
        if (it + 2 < NITER) { load_stage(it + 2, (it + 2) % 3); CP_COMMIT(); }
    }

    // ======================= epilogue A ====================================
    float* Zs = dyn;                       // [BM][ZSTRIDE]
    float* Pb0 = dyn + ZS_F;               // P chunk buffers
    const uint32_t pb0u = dynb + ZS_F * 4;

    // zero pad rows (classes 100..111) of both P chunk buffers
    for (int i = tid; i < 2 * 12 * PSTRIDE; i += 256) {
        const int buf = i / (12 * PSTRIDE);
        const int j   = i % (12 * PSTRIDE);
        Pb0[buf * PCH_F + (CNUM + j / PSTRIDE) * PSTRIDE + (j % PSTRIDE)] = 0.0f;
    }

    // issue P chunk 0 (k in [0,32))
    auto load_pchunk = [&](int kc, int buf) {
        const uint32_t base = pb0u + buf * (PCH_F * 4);
#pragma unroll
        for (int i = 0; i < 4; i++) {
            const int c = tid + (i << 8);
            if (c < CNUM * 8) {
                const int row = c >> 3, seg = c & 7;
                CP_ASYNC16(base + row * (PSTRIDE * 4) + seg * 16,
                           P + (size_t)row * DDIM + kc * 32 + seg * 4);
            }
        }
    };
    load_pchunk(0, 0); CP_COMMIT();

    // bias + rowsq + store Z to smem
    {
        float rsum[4][2];
#pragma unroll
        for (int mi = 0; mi < 4; mi++) { rsum[mi][0] = 0.f; rsum[mi][1] = 0.f; }

#pragma unroll
        for (int mi = 0; mi < 4; mi++) {
            const int rowA = warp_m * 64 + mi * 16 + lq;
#pragma unroll
            for (int nj = 0; nj < 8; nj++) {
                const int n0 = warp_n * 64 + nj * 8 + 2 * lr;
                float v0 = acc[mi][nj][0] + s_bias[n0];
                float v1 = acc[mi][nj][1] + s_bias[n0 + 1];
                float v2 = acc[mi][nj][2] + s_bias[n0];
                float v3 = acc[mi][nj][3] + s_bias[n0 + 1];
                rsum[mi][0] += v0 * v0 + v1 * v1;
                rsum[mi][1] += v2 * v2 + v3 * v3;
                *reinterpret_cast<float2*>(&Zs[rowA * ZSTRIDE + n0]) =
                    make_float2(v0, v1);
                *reinterpret_cast<float2*>(&Zs[(rowA + 8) * ZSTRIDE + n0]) =
                    make_float2(v2, v3);
            }
        }
#pragma unroll
        for (int mi = 0; mi < 4; mi++) {
#pragma unroll
            for (int h = 0; h < 2; h++) {
                float s = rsum[mi][h];
                s += __shfl_xor_sync(0xffffffffu, s, 1);
                s += __shfl_xor_sync(0xffffffffu, s, 2);
                if (lr == 0)
                    atomicAdd(&srow[warp_m * 64 + mi * 16 + lq + 8 * h], s);
            }
        }
    }

    // |P_c|^2 : warp w covers classes w*14 .. w*14+13 (>=100 -> 0)
#pragma unroll
    for (int i = 0; i < 14; i++) {
        const int c = wid * 14 + i;
        float s = 0.0f;
        if (c < CNUM) {
#pragma unroll
            for (int e = 0; e < 8; e++) {
                float t = P[(size_t)c * DDIM + e * 32 + lane];
                s += t * t;
            }
        }
        s += __shfl_xor_sync(0xffffffffu, s, 16);
        s += __shfl_xor_sync(0xffffffffu, s, 8);
        s += __shfl_xor_sync(0xffffffffu, s, 4);
        s += __shfl_xor_sync(0xffffffffu, s, 2);
        s += __shfl_xor_sync(0xffffffffu, s, 1);
        if (lane == 0) s_pn[c] = s;
    }

    // ======================= phase 2: MMA2 =================================
    const int warp_m2 = wid >> 1;   // 0..3 (32 rows each)
    const int warp_n2 = wid & 1;    // 0..1 (56 cols each)

    float acc2[2][7][4];
#pragma unroll
    for (int i = 0; i < 2; i++)
#pragma unroll
        for (int j = 0; j < 7; j++)
#pragma unroll
            for (int r = 0; r < 4; r++) acc2[i][j][r] = 0.0f;

    for (int kc = 0; kc < 8; kc++) {
        if (kc + 1 < 8) { load_pchunk(kc + 1, (kc + 1) & 1); CP_COMMIT(); }
        if (kc + 1 < 8) { CP_WAIT1(); } else { CP_WAIT0(); }
        __syncthreads();

        const float* Ps = Pb0 + (kc & 1) * PCH_F;
#pragma unroll
        for (int kk = 0; kk < 4; kk++) {
            const int kg = kc * 32 + kk * 8 + lr;   // global k for Zs
            uint32_t au[2][4], bu[7][2];
#pragma unroll
            for (int mi = 0; mi < 2; mi++) {
                const int row = warp_m2 * 32 + mi * 16 + lq;
                au[mi][0] = f2tf(Zs[row * ZSTRIDE + kg]);
                au[mi][1] = f2tf(Zs[(row + 8) * ZSTRIDE + kg]);
                au[mi][2] = f2tf(Zs[row * ZSTRIDE + kg + 4]);
                au[mi][3] = f2tf(Zs[(row + 8) * ZSTRIDE + kg + 4]);
            }
#pragma unroll
            for (int nj = 0; nj < 7; nj++) {
                const int c0 = warp_n2 * 56 + nj * 8 + lq;
                const int kl = kk * 8 + lr;
                bu[nj][0] = f2tf(Ps[c0 * PSTRIDE + kl]);
                bu[nj][1] = f2tf(Ps[c0 * PSTRIDE + kl + 4]);
            }
#pragma unroll
            for (int mi = 0; mi < 2; mi++)
#pragma unroll
                for (int nj = 0; nj < 7; nj++)
                    MMA_TF32(acc2[mi][nj], au[mi], bu[nj]);
        }
        __syncthreads();
    }

    // ======================= epilogue B ====================================
    const float inv = 1.0f / (float)DDIM;
#pragma unroll
    for (int mi = 0; mi < 2; mi++) {
        const int rowA = warp_m2 * 32 + mi * 16 + lq;
        const int rowB = rowA + 8;
        const float rsA = srow[rowA];
        const float rsB = srow[rowB];
#pragma unroll
        for (int nj = 0; nj < 7; nj++) {
            const int c0 = warp_n2 * 56 + nj * 8 + 2 * lr;
            const float pn0 = s_pn[c0];
            const float pn1 = s_pn[c0 + 1];
            if (c0 < CNUM)
                out[(size_t)(mBase + rowA) * CNUM + c0] =
                    (2.0f * acc2[mi][nj][0] - rsA - pn0) * inv;
            if (c0 + 1 < CNUM)
                out[(size_t)(mBase + rowA) * CNUM + c0 + 1] =
                    (2.0f * acc2[mi][nj][1] - rsA - pn1) * inv;
            if (c0 < CNUM)
                out[(size_t)(mBase + rowB) * CNUM + c0] =
                    (2.0f * acc2[mi][nj][2] - rsB - pn0) * inv;
            if (c0 + 1 < CNUM)
                out[(size_t)(mBase + rowB) * CNUM + c0 + 1] =
                    (2.0f * acc2[mi][nj][3] - rsB - pn1) * inv;
        }
    }
}

// ---------------------------------------------------------------------------
extern "C" void kernel_launch(void* const* d_in, const int* in_sizes, int n_in,
                              void* d_out, int out_size)
{
    const float* x  = (const float*)d_in[0];
    const float* W  = (const float*)d_in[1];
    const float* b  = (const float*)d_in[2];
    const float* P  = (const float*)d_in[3];
    float* out = (float*)d_out;

    cudaFuncSetAttribute(fused_kernel,
                         cudaFuncAttributeMaxDynamicSharedMemorySize, DYN_BYTES);

    fused_kernel<<<Bsz / BM, 256, DYN_BYTES>>>(x, W, b, P, out);
}

// round 4
// speedup vs baseline: 3.6416x; 1.0157x over previous
#include <cuda_runtime.h>
#include <cstdint>

// Problem: B=16384, IN_DIM=1024, D=256, C=100
#define Bsz    16384
#define KDIM   1024
#define DDIM   256
#define CNUM   100
#define CPAD   112

#define BM 128
#define BN 256
#define BK 32
#define NITER (KDIM / BK)   // 32
#define NTHREADS 512

#define ASTRIDE 36
#define BSTRIDE 264
#define ZSTRIDE 260
#define PSTRIDE 36

#define A_BYTES (BM * ASTRIDE * 4)        // 18432
#define B_BYTES (BK * BSTRIDE * 4)        // 33792
#define STAGE_BYTES (A_BYTES + B_BYTES)   // 52224
#define STAGE_F (STAGE_BYTES / 4)

#define ZS_F   (BM * ZSTRIDE)             // 33280
#define PCH_F  (CPAD * PSTRIDE)           // 4032
#define DYN_BYTES ((ZS_F + 2 * PCH_F) * 4)   // 165376 > 3*STAGE_BYTES

// ---------------------------------------------------------------------------
__device__ __forceinline__ uint32_t smem_u32(const void* p) {
    uint32_t a;
    asm("{ .reg .u64 t; cvta.to.shared.u64 t, %1; cvt.u32.u64 %0, t; }"
        : "=r"(a) : "l"(p));
    return a;
}

#define CP_ASYNC16(dst, src) \
    asm volatile("cp.async.cg.shared.global [%0], [%1], 16;" \
                 :: "r"(dst), "l"(src) : "memory")
#define CP_COMMIT() asm volatile("cp.async.commit_group;" ::: "memory")
#define CP_WAIT1()  asm volatile("cp.async.wait_group 1;" ::: "memory")
#define CP_WAIT0()  asm volatile("cp.async.wait_group 0;" ::: "memory")

// Raw fp32 bits fed to tf32 MMA: HW reads the top 19 bits (truncation).
#define F2U(x) __float_as_uint(x)

#define MMA_TF32(d, a, b) \
    asm volatile("mma.sync.aligned.m16n8k8.row.col.f32.tf32.tf32.f32 " \
        "{%0,%1,%2,%3}, {%4,%5,%6,%7}, {%8,%9}, {%0,%1,%2,%3};" \
        : "+f"((d)[0]), "+f"((d)[1]), "+f"((d)[2]), "+f"((d)[3]) \
        : "r"((a)[0]), "r"((a)[1]), "r"((a)[2]), "r"((a)[3]), \
          "r"((b)[0]), "r"((b)[1]))

// ---------------------------------------------------------------------------
// 512 threads / 16 warps.
// GEMM1 warp tile: 64 rows x 32 cols  (warp_m = wid&1, warp_n = wid>>1)
// MMA2  warp tile: 16 rows x 56 cols  (warp_m2 = wid>>1, warp_n2 = wid&1)
// ---------------------------------------------------------------------------
__global__ void __launch_bounds__(NTHREADS, 1)
fused_kernel(const float* __restrict__ x,
             const float* __restrict__ W,
             const float* __restrict__ bias,
             const float* __restrict__ P,
             float* __restrict__ out)
{
    extern __shared__ float dyn[];
    __shared__ float s_bias[DDIM];
    __shared__ float srow[BM];
    __shared__ float s_pn[CPAD];

    const int tid  = threadIdx.x;
    const int wid  = tid >> 5;
    const int lane = tid & 31;
    const int mBase = blockIdx.x * BM;

    const int warp_m = wid & 1;    // 0..1 : 64 rows
    const int warp_n = wid >> 1;   // 0..7 : 32 cols

    if (tid < DDIM) s_bias[tid] = bias[tid];
    if (tid < BM)   srow[tid] = 0.0f;

    const uint32_t dynb = smem_u32(dyn);

    // ---- stage loader (GEMM1): A 1024 chunks, B 2048 chunks of 16B ----
    auto load_stage = [&](int kIter, int slot) {
        const int k0 = kIter * BK;
        const uint32_t aB = dynb + slot * STAGE_BYTES;
        const uint32_t bB = aB + A_BYTES;
#pragma unroll
        for (int i = 0; i < 2; i++) {
            const int c = tid + (i << 9);
            const int row = c >> 3, seg = c & 7;
            CP_ASYNC16(aB + row * (ASTRIDE * 4) + seg * 16,
                       x + (size_t)(mBase + row) * KDIM + k0 + seg * 4);
        }
#pragma unroll
        for (int i = 0; i < 4; i++) {
            const int c = tid + (i << 9);
            const int k = c >> 6, seg = c & 63;
            CP_ASYNC16(bB + k * (BSTRIDE * 4) + seg * 16,
                       W + (size_t)(k0 + k) * DDIM + seg * 4);
        }
    };

    load_stage(0, 0); CP_COMMIT();
    load_stage(1, 1); CP_COMMIT();

    float acc[4][4][4];
#pragma unroll
    for (int i = 0; i < 4; i++)
#pragma unroll
        for (int j = 0; j < 4; j++)
#pragma unroll
            for (int r = 0; r < 4; r++) acc[i][j][r] = 0.0f;

    const int lq = lane >> 2;
    const int lr = lane & 3;

    // ---- GEMM1 mainloop ----
    for (int it = 0; it < NITER; ++it) {
        if (it == NITER - 1) { CP_WAIT0(); } else { CP_WAIT1(); }
        __syncthreads();

        const float* As = dyn + (it % 3) * STAGE_F;
        const float* Bs = As + A_BYTES / 4;
        // per-thread bases (immediates handle the rest)
        const float* aP = As + (warp_m * 64 + lq) * ASTRIDE + lr;
        const float* bP = Bs + lr * BSTRIDE + warp_n * 32 + lq;

#pragma unroll
        for (int kk = 0; kk < 4; kk++) {
            uint32_t au[4][4], bu[4][2];
#pragma unroll
            for (int mi = 0; mi < 4; mi++) {
                const float* p = aP + mi * 16 * ASTRIDE + kk * 8;
                au[mi][0] = F2U(p[0]);
                au[mi][1] = F2U(p[8 * ASTRIDE]);
                au[mi][2] = F2U(p[4]);
                au[mi][3] = F2U(p[8 * ASTRIDE + 4]);
            }
#pragma unroll
            for (int nj = 0; nj < 4; nj++) {
                const float* p = bP + kk * 8 * BSTRIDE + nj * 8;
                bu[nj][0] = F2U(p[0]);
                bu[nj][1] = F2U(p[4 * BSTRIDE]);
            }
#pragma unroll
            for (int mi = 0; mi < 4; mi++)
#pragma unroll
                for (int nj = 0; nj < 4; nj++)
                    MMA_TF32(acc[mi][nj], au[mi], bu[nj]);
        }
        __syncthreads();
        if (it + 2 < NITER) { load_stage(it + 2, (it + 2) % 3); CP_COMMIT(); }
    }

    // ======================= epilogue A ====================================
    float* Zs  = dyn;                      // [BM][ZSTRIDE]
    float* Pb0 = dyn + ZS_F;
    const uint32_t pb0u = dynb + ZS_F * 4;

    // zero pad rows (classes 100..111) of both P chunk buffers
    for (int i = tid; i < 2 * 12 * PSTRIDE; i += NTHREADS) {
        const int buf = i / (12 * PSTRIDE);
        const int j   = i % (12 * PSTRIDE);
        Pb0[buf * PCH_F + (CNUM + j / PSTRIDE) * PSTRIDE + (j % PSTRIDE)] = 0.0f;
    }

    auto load_pchunk = [&](int kc, int buf) {
        const uint32_t base = pb0u + buf * (PCH_F * 4);
#pragma unroll
        for (int i = 0; i < 2; i++) {
            const int c = tid + (i << 9);
            if (c < CNUM * 8) {
                const int row = c >> 3, seg = c & 7;
                CP_ASYNC16(base + row * (PSTRIDE * 4) + seg * 16,
                           P + (size_t)row * DDIM + kc * 32 + seg * 4);
            }
        }
    };
    load_pchunk(0, 0); CP_COMMIT();

    // bias + rowsq + Z -> smem
    {
        float rsum[4][2];
#pragma unroll
        for (int mi = 0; mi < 4; mi++) { rsum[mi][0] = 0.f; rsum[mi][1] = 0.f; }

#pragma unroll
        for (int mi = 0; mi < 4; mi++) {
            const int rowA = warp_m * 64 + mi * 16 + lq;
#pragma unroll
            for (int nj = 0; nj < 4; nj++) {
                const int n0 = warp_n * 32 + nj * 8 + 2 * lr;
                float v0 = acc[mi][nj][0] + s_bias[n0];
                float v1 = acc[mi][nj][1] + s_bias[n0 + 1];
                float v2 = acc[mi][nj][2] + s_bias[n0];
                float v3 = acc[mi][nj][3] + s_bias[n0 + 1];
                rsum[mi][0] += v0 * v0 + v1 * v1;
                rsum[mi][1] += v2 * v2 + v3 * v3;
                *reinterpret_cast<float2*>(&Zs[rowA * ZSTRIDE + n0]) =
                    make_float2(v0, v1);
                *reinterpret_cast<float2*>(&Zs[(rowA + 8) * ZSTRIDE + n0]) =
                    make_float2(v2, v3);
            }
        }
#pragma unroll
        for (int mi = 0; mi < 4; mi++) {
#pragma unroll
            for (int h = 0; h < 2; h++) {
                float s = rsum[mi][h];
                s += __shfl_xor_sync(0xffffffffu, s, 1);
                s += __shfl_xor_sync(0xffffffffu, s, 2);
                if (lr == 0)
                    atomicAdd(&srow[warp_m * 64 + mi * 16 + lq + 8 * h], s);
            }
        }
    }

    // |P_c|^2 : warp w covers classes w*7 .. w*7+6  (16*7 = 112 = CPAD)
#pragma unroll
    for (int i = 0; i < 7; i++) {
        const int c = wid * 7 + i;
        float s = 0.0f;
        if (c < CNUM) {
#pragma unroll
            for (int e = 0; e < 8; e++) {
                float t = P[(size_t)c * DDIM + e * 32 + lane];
                s += t * t;
            }
        }
        s += __shfl_xor_sync(0xffffffffu, s, 16);
        s += __shfl_xor_sync(0xffffffffu, s, 8);
        s += __shfl_xor_sync(0xffffffffu, s, 4);
        s += __shfl_xor_sync(0xffffffffu, s, 2);
        s += __shfl_xor_sync(0xffffffffu, s, 1);
        if (lane == 0) s_pn[c] = s;
    }

    // ======================= phase 2: MMA2 =================================
    const int warp_m2 = wid >> 1;   // 0..7 : 16 rows
    const int warp_n2 = wid & 1;    // 0..1 : 56 cols

    float acc2[7][4];
#pragma unroll
    for (int j = 0; j < 7; j++)
#pragma unroll
        for (int r = 0; r < 4; r++) acc2[j][r] = 0.0f;

    const int zrow = warp_m2 * 16 + lq;

    for (int kc = 0; kc < 8; kc++) {
        if (kc + 1 < 8) { load_pchunk(kc + 1, (kc + 1) & 1); CP_COMMIT(); }
        if (kc + 1 < 8) { CP_WAIT1(); } else { CP_WAIT0(); }
        __syncthreads();

        const float* Ps = Pb0 + (kc & 1) * PCH_F;
        const float* pP = Ps + (warp_n2 * 56 + lq) * PSTRIDE + lr;
        const float* zP = Zs + zrow * ZSTRIDE + kc * 32 + lr;

#pragma unroll
        for (int kk = 0; kk < 4; kk++) {
            uint32_t au[4], bu[7][2];
            const float* zp = zP + kk * 8;
            au[0] = F2U(zp[0]);
            au[1] = F2U(zp[8 * ZSTRIDE]);
            au[2] = F2U(zp[4]);
            au[3] = F2U(zp[8 * ZSTRIDE + 4]);
#pragma unroll
            for (int nj = 0; nj < 7; nj++) {
                const float* p = pP + nj * 8 * PSTRIDE + kk * 8;
                bu[nj][0] = F2U(p[0]);
                bu[nj][1] = F2U(p[4]);
            }
#pragma unroll
            for (int nj = 0; nj < 7; nj++)
                MMA_TF32(acc2[nj], au, bu[nj]);
        }
        __syncthreads();
    }

    // ======================= epilogue B ====================================
    const float inv = 1.0f / (float)DDIM;
    const int rowA = warp_m2 * 16 + lq;
    const int rowB = rowA + 8;
    const float rsA = srow[rowA];
    const float rsB = srow[rowB];
#pragma unroll
    for (int nj = 0; nj < 7; nj++) {
        const int c0 = warp_n2 * 56 + nj * 8 + 2 * lr;
        const float pn0 = s_pn[c0];
        const float pn1 = s_pn[c0 + 1];
        if (c0 < CNUM)
            out[(size_t)(mBase + rowA) * CNUM + c0] =
                (2.0f * acc2[nj][0] - rsA - pn0) * inv;
        if (c0 + 1 < CNUM)
            out[(size_t)(mBase + rowA) * CNUM + c0 + 1] =
                (2.0f * acc2[nj][1] - rsA - pn1) * inv;
        if (c0 < CNUM)
            out[(size_t)(mBase + rowB) * CNUM + c0] =
                (2.0f * acc2[nj][2] - rsB - pn0) * inv;
        if (c0 + 1 < CNUM)
            out[(size_t)(mBase + rowB) * CNUM + c0 + 1] =
                (2.0f * acc2[nj][3] - rsB - pn1) * inv;
    }
}

// ---------------------------------------------------------------------------
extern "C" void kernel_launch(void* const* d_in, const int* in_sizes, int n_in,
                              void* d_out, int out_size)
{
    const float* x  = (const float*)d_in[0];
    const float* W  = (const float*)d_in[1];
    const float* b  = (const float*)d_in[2];
    const float* P  = (const float*)d_in[3];
    float* out = (float*)d_out;

    cudaFuncSetAttribute(fused_kernel,
                         cudaFuncAttributeMaxDynamicSharedMemorySize, DYN_BYTES);

    fused_kernel<<<Bsz / BM, NTHREADS, DYN_BYTES>>>(x, W, b, P, out);
}